// round 4
// baseline (speedup 1.0000x reference)
#include <cuda_runtime.h>
#include <cstdint>
#include <math.h>

#define B_SZ  32
#define T_LEN 2048
#define I_DIM 128
#define H_DIM 256
#define N_TOK (B_SZ * T_LEN)   // 65536

// Scratch (device globals: allocation-free rule)
__device__ float g_xB[(size_t)N_TOK * H_DIM];   // 64 MB
__device__ float g_hs[(size_t)N_TOK * H_DIM];   // 64 MB

// ---------------------------------------------------------------------------
// helpers
// ---------------------------------------------------------------------------
__device__ __forceinline__ void fma2(unsigned long long& acc,
                                     unsigned long long a,
                                     unsigned long long b) {
    asm("fma.rn.f32x2 %0, %1, %2, %0;" : "+l"(acc) : "l"(a), "l"(b));
}
__device__ __forceinline__ float lo_f(unsigned long long u) {
    return __uint_as_float((unsigned)(u & 0xffffffffull));
}
__device__ __forceinline__ float hi_f(unsigned long long u) {
    return __uint_as_float((unsigned)(u >> 32));
}
__device__ __forceinline__ unsigned long long pack2(float l, float h) {
    return (unsigned long long)__float_as_uint(l) |
           ((unsigned long long)__float_as_uint(h) << 32);
}

// ---------------------------------------------------------------------------
// fp32 tiled GEMM (round-2 version, scalar FFMA): Y[M,N] = X[M,K] @ W[K,N]
// BM=128, BN=64, BK=16, 256 threads, 8x4 micro-tile per thread.
// ---------------------------------------------------------------------------
__global__ void __launch_bounds__(256) gemm_kernel(const float* __restrict__ X,
                                                   const float* __restrict__ W,
                                                   float* __restrict__ Y,
                                                   int M, int K, int N) {
    __shared__ float Xs[16][128];
    __shared__ float Ws[16][64];

    const int tid = threadIdx.x;
    const int m0 = blockIdx.x * 128;
    const int n0 = blockIdx.y * 64;
    const int tx = tid & 15;
    const int ty = tid >> 4;

    float acc[8][4];
#pragma unroll
    for (int r = 0; r < 8; r++)
#pragma unroll
        for (int cc = 0; cc < 4; cc++) acc[r][cc] = 0.f;

    const int lrow  = tid >> 1;
    const int lpart = (tid & 1) * 8;

    for (int kt = 0; kt < K; kt += 16) {
        const float* xp = X + (size_t)(m0 + lrow) * K + kt + lpart;
        float4 v0 = *(const float4*)(xp);
        float4 v1 = *(const float4*)(xp + 4);
        Xs[lpart + 0][lrow] = v0.x;
        Xs[lpart + 1][lrow] = v0.y;
        Xs[lpart + 2][lrow] = v0.z;
        Xs[lpart + 3][lrow] = v0.w;
        Xs[lpart + 4][lrow] = v1.x;
        Xs[lpart + 5][lrow] = v1.y;
        Xs[lpart + 6][lrow] = v1.z;
        Xs[lpart + 7][lrow] = v1.w;
        {
            const int wk = tid >> 4;
            const int wn = (tid & 15) * 4;
            float4 wv = *(const float4*)(W + (size_t)(kt + wk) * N + n0 + wn);
            *(float4*)&Ws[wk][wn] = wv;
        }
        __syncthreads();

#pragma unroll
        for (int k = 0; k < 16; k++) {
            float4 xa = *(const float4*)&Xs[k][ty * 8];
            float4 xb = *(const float4*)&Xs[k][ty * 8 + 4];
            float4 wv = *(const float4*)&Ws[k][tx * 4];
            float xr[8] = {xa.x, xa.y, xa.z, xa.w, xb.x, xb.y, xb.z, xb.w};
            float wr[4] = {wv.x, wv.y, wv.z, wv.w};
#pragma unroll
            for (int r = 0; r < 8; r++)
#pragma unroll
                for (int cc = 0; cc < 4; cc++)
                    acc[r][cc] = fmaf(xr[r], wr[cc], acc[r][cc]);
        }
        __syncthreads();
    }

#pragma unroll
    for (int r = 0; r < 8; r++) {
        float4 o = make_float4(acc[r][0], acc[r][1], acc[r][2], acc[r][3]);
        *(float4*)&Y[(size_t)(m0 + ty * 8 + r) * N + n0 + tx * 4] = o;
    }
}

// ---------------------------------------------------------------------------
// Scan kernel: one CTA per batch. 512 threads.
// Thread (g = tid>>3, c = tid&7): owns columns 4g..4g+3, k-window
// [c*32, c*32+32). Per column: 24 A-values in registers (f32x2 pairs),
// 8 A-values streamed from smem (lane-consecutive double2 slots).
// h double-buffered in smem with a 16B skew every 32 floats so the 8
// c-windows read conflict-free at full crossbar width.
// ---------------------------------------------------------------------------
#define HSK  288                        // 256 + 8*4 skew floats per buffer
__device__ __forceinline__ int hskew(int k) { return k + ((k >> 5) << 2); }

__global__ void __launch_bounds__(512) scan_kernel(const float* __restrict__ A) {
    extern __shared__ float smem[];
    float*   hbuf = smem;                        // [2][288]
    double2* As   = (double2*)(smem + 2 * HSK);  // [8][512] double2 = 64 KB

    const int tid = threadIdx.x;
    const int b   = blockIdx.x;
    const int g   = tid >> 3;     // 0..63 -> cols 4g..4g+3
    const int c   = tid & 7;      // 0..7  -> k window [32c, 32c+32)
    const int k0  = c * 32;
    const int col0 = g * 4;

    // A into registers: per col, pairs (k0+2q, k0+2q+1) for q in [0,12)
    unsigned long long a2[4][12];
#pragma unroll
    for (int cc = 0; cc < 4; cc++) {
        const float* Ac = A + (size_t)k0 * H_DIM + col0 + cc;
#pragma unroll
        for (int q = 0; q < 12; q++)
            a2[cc][q] = pack2(Ac[(size_t)(2 * q) * H_DIM],
                              Ac[(size_t)(2 * q + 1) * H_DIM]);
        // A tail (k_rel 24..31) into smem as double2 chunks
#pragma unroll
        for (int ph = 0; ph < 2; ph++) {
            const float* At = Ac + (size_t)(24 + 4 * ph) * H_DIM;
            double2 d;
            d.x = __longlong_as_double(pack2(At[0], At[H_DIM]));
            d.y = __longlong_as_double(pack2(At[2 * H_DIM], At[3 * H_DIM]));
            As[(cc * 2 + ph) * 512 + tid] = d;
        }
    }
    // h0 = 0
    for (int i = tid; i < 2 * HSK; i += 512) hbuf[i] = 0.f;
    __syncthreads();

    const float* xB = g_xB + (size_t)b * T_LEN * H_DIM;
    float*       hs = g_hs + (size_t)b * T_LEN * H_DIM;

    float4 xb_cur = make_float4(0.f, 0.f, 0.f, 0.f);
    if (c == 0) xb_cur = *(const float4*)(xB + col0);

    for (int s = 0; s < T_LEN; s++) {
        const int rb = s & 1;
        float4 xb_nxt;
        if (c == 0 && s + 1 < T_LEN)
            xb_nxt = *(const float4*)(xB + (size_t)(s + 1) * H_DIM + col0);

        // dot over this thread's 32-k window for 4 columns
        const double2* hp = (const double2*)(hbuf + rb * HSK + c * 36);
        unsigned long long acc0 = 0ull, acc1 = 0ull, acc2 = 0ull, acc3 = 0ull;
#pragma unroll
        for (int q = 0; q < 6; q++) {
            double2 hv = hp[q];
            unsigned long long hlo = (unsigned long long)__double_as_longlong(hv.x);
            unsigned long long hhi = (unsigned long long)__double_as_longlong(hv.y);
            fma2(acc0, a2[0][2 * q], hlo); fma2(acc0, a2[0][2 * q + 1], hhi);
            fma2(acc1, a2[1][2 * q], hlo); fma2(acc1, a2[1][2 * q + 1], hhi);
            fma2(acc2, a2[2][2 * q], hlo); fma2(acc2, a2[2][2 * q + 1], hhi);
            fma2(acc3, a2[3][2 * q], hlo); fma2(acc3, a2[3][2 * q + 1], hhi);
        }
#pragma unroll
        for (int ph = 0; ph < 2; ph++) {
            double2 hv = hp[6 + ph];
            unsigned long long hlo = (unsigned long long)__double_as_longlong(hv.x);
            unsigned long long hhi = (unsigned long long)__double_as_longlong(hv.y);
#pragma unroll
            for (int cc = 0; cc < 4; cc++) {
                double2 av = As[(cc * 2 + ph) * 512 + tid];
                unsigned long long alo = (unsigned long long)__double_as_longlong(av.x);
                unsigned long long ahi = (unsigned long long)__double_as_longlong(av.y);
                unsigned long long* accp = (cc == 0) ? &acc0 : (cc == 1) ? &acc1
                                         : (cc == 2) ? &acc2 : &acc3;
                fma2(*accp, alo, hlo);
                fma2(*accp, ahi, hhi);
            }
        }

        float sv[4];
        sv[0] = lo_f(acc0) + hi_f(acc0);
        sv[1] = lo_f(acc1) + hi_f(acc1);
        sv[2] = lo_f(acc2) + hi_f(acc2);
        sv[3] = lo_f(acc3) + hi_f(acc3);
#pragma unroll
        for (int d = 1; d < 8; d <<= 1) {
#pragma unroll
            for (int cc = 0; cc < 4; cc++)
                sv[cc] += __shfl_xor_sync(0xffffffffu, sv[cc], d);
        }

        if (c == 0) {
            float4 y;
            y.x = tanhf(sv[0] + xb_cur.x);
            y.y = tanhf(sv[1] + xb_cur.y);
            y.z = tanhf(sv[2] + xb_cur.z);
            y.w = tanhf(sv[3] + xb_cur.w);
            *(float4*)(hbuf + (rb ^ 1) * HSK + hskew(col0)) = y;
            *(float4*)(hs + (size_t)s * H_DIM + col0) = y;
            xb_cur = xb_nxt;
        }
        __syncthreads();
    }
}

// ---------------------------------------------------------------------------
extern "C" void kernel_launch(void* const* d_in, const int* in_sizes, int n_in,
                              void* d_out, int out_size) {
    const float* x  = (const float*)d_in[0];   // [32,2048,128]
    const float* A  = (const float*)d_in[1];   // [256,256]
    const float* Bm = (const float*)d_in[2];   // [128,256]
    const float* C  = (const float*)d_in[3];   // [256,256]
    float* out = (float*)d_out;                // [32,2048,256]

    float* xBp = nullptr;
    float* hsp = nullptr;
    cudaGetSymbolAddress((void**)&xBp, g_xB);
    cudaGetSymbolAddress((void**)&hsp, g_hs);

    const int scan_smem = 2 * HSK * 4 + 8 * 512 * 16;   // 2304 + 65536 B
    cudaFuncSetAttribute(scan_kernel,
                         cudaFuncAttributeMaxDynamicSharedMemorySize, scan_smem);

    // 1) xB = x @ Bm : [65536,128] @ [128,256]
    gemm_kernel<<<dim3(N_TOK / 128, H_DIM / 64), 256>>>(x, Bm, xBp, N_TOK, I_DIM, H_DIM);
    // 2) sequential scan over T, one CTA per batch
    scan_kernel<<<B_SZ, 512, scan_smem>>>(A);
    // 3) out = hs @ C : [65536,256] @ [256,256]
    gemm_kernel<<<dim3(N_TOK / 128, H_DIM / 64), 256>>>(hsp, C, out, N_TOK, H_DIM, H_DIM);
}